// round 12
// baseline (speedup 1.0000x reference)
#include <cuda_runtime.h>

// img: [256, 3, 224, 224] f32, y_idx/x_idx: [256] i32.
// out[b,c,h,w] = img * (0 if h in [y,y+32) && w in [x,x+32) else 1)
//
// MLP-axis probe: tiled 56-row blocks, each thread front-batches 14 float4
// loads (rows h0 + 4k, k=0..13). No launch-bounds reg cap (R10 lesson:
// capping regs serializes the load batch). ~200+ KB/SM in flight vs R3's
// ~172 KB. If flat/regressed, R3 (RPT=8) is the confirmed final champion.

#define SQ 32
#define BATCH 256
#define CH 3
#define HH 224
#define WW 224
#define W4 (WW / 4)                    // 56 float4 per row
#define TY 4                           // threads in y
#define RPT 14                         // rows per thread
#define TILE_H (TY * RPT)              // 56 rows per block

__global__ __launch_bounds__(W4 * TY)
void random_square_dropout_kernel(const float4* __restrict__ img,
                                  const int* __restrict__ y_idx,
                                  const int* __restrict__ x_idx,
                                  float4* __restrict__ out) {
    const int b  = blockIdx.z;
    const int c  = blockIdx.y;
    const int h0 = blockIdx.x * TILE_H + threadIdx.y;  // rows h0 + TY*k
    const int w4 = threadIdx.x;                        // 0..55

    const int y = __ldg(&y_idx[b]);
    const int x = __ldg(&x_idx[b]);

    const long plane = ((long)b * CH + c) * (long)(HH * W4);
    const long base  = plane + (long)h0 * W4 + w4;

    // Front-batched loads: 14 independent DRAM requests in flight per thread.
    float4 v[RPT];
#pragma unroll
    for (int k = 0; k < RPT; k++)
        v[k] = __ldcs(&img[base + (long)(k * TY) * W4]);

    // Column in-square flags (constant across this thread's rows).
    const int w0 = w4 * 4;
    const bool cx0 = (unsigned)(w0     - x) < SQ;
    const bool cx1 = (unsigned)(w0 + 1 - x) < SQ;
    const bool cx2 = (unsigned)(w0 + 2 - x) < SQ;
    const bool cx3 = (unsigned)(w0 + 3 - x) < SQ;

    if (cx0 || cx1 || cx2 || cx3) {
#pragma unroll
        for (int k = 0; k < RPT; k++) {
            const int h = h0 + k * TY;
            if ((unsigned)(h - y) < SQ) {
                if (cx0) v[k].x = 0.f;
                if (cx1) v[k].y = 0.f;
                if (cx2) v[k].z = 0.f;
                if (cx3) v[k].w = 0.f;
            }
        }
    }

#pragma unroll
    for (int k = 0; k < RPT; k++)
        __stcs(&out[base + (long)(k * TY) * W4], v[k]);
}

extern "C" void kernel_launch(void* const* d_in, const int* in_sizes, int n_in,
                              void* d_out, int out_size) {
    const float4* img = (const float4*)d_in[0];
    const int* y_idx  = (const int*)d_in[1];
    const int* x_idx  = (const int*)d_in[2];
    float4* out       = (float4*)d_out;

    dim3 block(W4, TY);                      // 56 x 4 = 224 threads
    dim3 grid(HH / TILE_H, CH, BATCH);       // 4 x 3 x 256 = 3072 blocks
    random_square_dropout_kernel<<<grid, block>>>(img, y_idx, x_idx, out);
}

// round 13
// speedup vs baseline: 1.0052x; 1.0052x over previous
#include <cuda_runtime.h>

// img: [256, 3, 224, 224] f32, y_idx/x_idx: [256] i32.
// out[b,c,h,w] = img * (0 if h in [y,y+32) && w in [x,x+32) else 1)
//
// FINAL champion (R3/R11 config). Evidence from 12 rounds: this op is pinned
// at the GB300 mixed-R/W HBM ceiling (~6.1 TB/s, 75-78% of spec) regardless
// of structure (tiled/persistent/flat), MLP (4/8/14), vector width (128/256b),
// cache policy (__ldcs/__stcs/evict hints), engine (SM vs CE), or occupancy
// (34-84%). Config: tiled 32-row blocks, 224 threads (TY=4), 8 front-batched
// coalesced float4 __ldcs loads per thread, predicated unsigned-range masking,
// __stcs stores. 46-48 regs / 6 CTAs/SM — the proven optimum of the
// MLP-vs-occupancy trade (reg-capping serializes the load batch; higher
// occupancy adds cross-CTA L1tex-queue spread).

#define SQ 32
#define BATCH 256
#define CH 3
#define HH 224
#define WW 224
#define W4 (WW / 4)                    // 56 float4 per row
#define TY 4                           // threads in y
#define RPT 8                          // rows per thread
#define TILE_H (TY * RPT)              // 32 rows per block

__global__ __launch_bounds__(W4 * TY)
void random_square_dropout_kernel(const float4* __restrict__ img,
                                  const int* __restrict__ y_idx,
                                  const int* __restrict__ x_idx,
                                  float4* __restrict__ out) {
    const int b  = blockIdx.z;
    const int c  = blockIdx.y;
    const int h0 = blockIdx.x * TILE_H + threadIdx.y;  // rows h0 + TY*k
    const int w4 = threadIdx.x;                        // 0..55

    const int y = __ldg(&y_idx[b]);
    const int x = __ldg(&x_idx[b]);

    const long plane = ((long)b * CH + c) * (long)(HH * W4);
    const long base  = plane + (long)h0 * W4 + w4;

    // Front-batched loads: 8 independent DRAM requests in flight per thread.
    float4 v[RPT];
#pragma unroll
    for (int k = 0; k < RPT; k++)
        v[k] = __ldcs(&img[base + (long)(k * TY) * W4]);

    // Column in-square flags (constant across this thread's rows).
    const int w0 = w4 * 4;
    const bool cx0 = (unsigned)(w0     - x) < SQ;
    const bool cx1 = (unsigned)(w0 + 1 - x) < SQ;
    const bool cx2 = (unsigned)(w0 + 2 - x) < SQ;
    const bool cx3 = (unsigned)(w0 + 3 - x) < SQ;

    if (cx0 || cx1 || cx2 || cx3) {
#pragma unroll
        for (int k = 0; k < RPT; k++) {
            const int h = h0 + k * TY;
            if ((unsigned)(h - y) < SQ) {
                if (cx0) v[k].x = 0.f;
                if (cx1) v[k].y = 0.f;
                if (cx2) v[k].z = 0.f;
                if (cx3) v[k].w = 0.f;
            }
        }
    }

#pragma unroll
    for (int k = 0; k < RPT; k++)
        __stcs(&out[base + (long)(k * TY) * W4], v[k]);
}

extern "C" void kernel_launch(void* const* d_in, const int* in_sizes, int n_in,
                              void* d_out, int out_size) {
    const float4* img = (const float4*)d_in[0];
    const int* y_idx  = (const int*)d_in[1];
    const int* x_idx  = (const int*)d_in[2];
    float4* out       = (float4*)d_out;

    dim3 block(W4, TY);                      // 56 x 4 = 224 threads
    dim3 grid(HH / TILE_H, CH, BATCH);       // 7 x 3 x 256 = 5376 blocks
    random_square_dropout_kernel<<<grid, block>>>(img, y_idx, x_idx, out);
}